// round 4
// baseline (speedup 1.0000x reference)
#include <cuda_runtime.h>
#include <cstdint>

#define NN 100000
#define DD 256
#define EE 3200000
#define LN_EPS 1e-5f

// -------- scratch (static device globals; no runtime allocation) --------
__device__ __align__(16) float g_h   [(size_t)NN * DD];   // current features
__device__ __align__(16) float g_xw  [(size_t)NN * DD];   // h @ W
__device__ float g_deg [NN];
__device__ float g_dis [NN];
__device__ float g_ew  [EE];
__device__ int   g_cnt [NN];                // in-degree per dst
__device__ int   g_off [NN];                // CSR segment start per dst
__device__ int   g_cur [NN];                // fill cursor per dst
__device__ int   g_erow [EE];               // CSR: source node per slot
__device__ float g_enorm[EE];               // CSR: edge norm per slot
__device__ int   g_total;                   // base for segment placement
__device__ int   g_is64;                    // edge_index dtype flag

// fast-math-safe finite check (bit pattern, cannot be folded away)
__device__ __forceinline__ float fsafe(float v) {
    unsigned u = __float_as_uint(v);
    return ((u & 0x7f800000u) == 0x7f800000u) ? 0.0f : v;
}

// -------- dtype detection: int64 vs int32 edge_index --------
// If data is int64, every odd 32-bit word is a (zero) high word.
// Sample two windows to be robust.
__global__ void detect_kernel(const int* __restrict__ ei32) {
    __shared__ int cnt;
    if (threadIdx.x == 0) cnt = 0;
    __syncthreads();
    int nz = 0;
    for (int k = threadIdx.x; k < 2048; k += blockDim.x) {
        if (ei32[2 * k + 1] != 0) nz++;                      // window 1: start
        if (ei32[2 * (EE / 2 + k) + 1] != 0) nz++;           // window 2: middle
    }
    atomicAdd(&cnt, nz);                                      // shared atomic
    __syncthreads();
    if (threadIdx.x == 0) g_is64 = (cnt < 2048) ? 1 : 0;
}

__device__ __forceinline__ int load_idx(const void* ei, size_t pos, int is64) {
    if (is64) return (int)((const long long*)ei)[pos];
    return ((const int*)ei)[pos];
}

// -------- prep: safe edge weights + zero counters --------
__global__ void prep_kernel(const float* __restrict__ ew_in) {
    int i = blockIdx.x * blockDim.x + threadIdx.x;
    if (i < EE) g_ew[i] = fmaxf(fabsf(fsafe(ew_in[i])), 1e-6f);
    if (i < NN) { g_deg[i] = 0.0f; g_cnt[i] = 0; g_cur[i] = 0; }
    if (i == 0) g_total = 0;
}

// -------- degree + count accumulation over dst (col) --------
__global__ void deg_kernel(const void* __restrict__ ei) {
    int e = blockIdx.x * blockDim.x + threadIdx.x;
    if (e >= EE) return;
    int is64 = g_is64;
    int c = load_idx(ei, (size_t)EE + e, is64);
    if ((unsigned)c < NN) {
        atomicAdd(&g_deg[c], g_ew[e]);
        atomicAdd(&g_cnt[c], 1);
    }
}

// -------- dis = rsqrt(deg + 1) --------
__global__ void dis_kernel() {
    int i = blockIdx.x * blockDim.x + threadIdx.x;
    if (i < NN) g_dis[i] = rsqrtf(g_deg[i] + 1.0f);
}

// -------- segment placement: per-block scan + one atomic per block --------
__global__ void scan_kernel() {
    __shared__ int warp_tot[8];
    __shared__ int blk_base;
    int n = blockIdx.x * 256 + threadIdx.x;
    int lane = threadIdx.x & 31, w = threadIdx.x >> 5;

    int c = (n < NN) ? g_cnt[n] : 0;
    int incl = c;
    #pragma unroll
    for (int o = 1; o < 32; o <<= 1) {
        int t = __shfl_up_sync(0xffffffffu, incl, o);
        if (lane >= o) incl += t;
    }
    if (lane == 31) warp_tot[w] = incl;
    __syncthreads();
    if (w == 0) {
        int t = (lane < 8) ? warp_tot[lane] : 0;
        #pragma unroll
        for (int o = 1; o < 8; o <<= 1) {
            int u = __shfl_up_sync(0xffffffffu, t, o);
            if (lane >= o) t += u;
        }
        if (lane < 8) warp_tot[lane] = t;
        if (lane == 7) blk_base = atomicAdd(&g_total, t);
    }
    __syncthreads();
    int prefix = blk_base + (w > 0 ? warp_tot[w - 1] : 0) + incl - c;
    if (n < NN) g_off[n] = prefix;
}

// -------- CSR fill: place (row, norm) into dst segment --------
__global__ void fill_kernel(const void* __restrict__ ei) {
    int e = blockIdx.x * blockDim.x + threadIdx.x;
    if (e >= EE) return;
    int is64 = g_is64;
    int r = load_idx(ei, (size_t)e, is64);
    int c = load_idx(ei, (size_t)EE + e, is64);
    if ((unsigned)r >= NN || (unsigned)c >= NN) return;
    float norm = g_dis[r] * g_ew[e] * g_dis[c];
    int p = atomicAdd(&g_cur[c], 1);
    int slot = g_off[c] + p;
    if ((unsigned)slot < EE) {
        g_erow[slot]  = r;
        g_enorm[slot] = norm;
    }
}

// -------- h = safe(x) --------
__global__ void copyx_kernel(const float* __restrict__ x) {
    size_t i = (size_t)blockIdx.x * blockDim.x + threadIdx.x;
    if (i < (size_t)NN * DD) g_h[i] = fsafe(x[i]);
}

// -------- SGEMM: g_xw = g_h @ W  (M=NN, N=DD, K=DD), W row-major [K,N] --------
__global__ void sgemm_kernel(const float* __restrict__ W) {
    __shared__ float As[16][64];
    __shared__ float Bs[16][64];

    const int m0 = blockIdx.x * 64;
    const int n0 = blockIdx.y * 64;
    const int tid = threadIdx.x;
    const int tx = tid & 15;
    const int ty = tid >> 4;
    const int arow = tid >> 2;
    const int ac4  = (tid & 3) * 4;
    const int brow = tid >> 4;
    const int bc4  = (tid & 15) * 4;

    float acc[4][4] = {};

    for (int k0 = 0; k0 < DD; k0 += 16) {
        float4 av = make_float4(0.f, 0.f, 0.f, 0.f);
        int gr = m0 + arow;
        if (gr < NN) av = *(const float4*)(g_h + (size_t)gr * DD + k0 + ac4);
        As[ac4 + 0][arow] = av.x;
        As[ac4 + 1][arow] = av.y;
        As[ac4 + 2][arow] = av.z;
        As[ac4 + 3][arow] = av.w;

        float4 bv = *(const float4*)(W + (size_t)(k0 + brow) * DD + n0 + bc4);
        *(float4*)&Bs[brow][bc4] = bv;

        __syncthreads();

        #pragma unroll
        for (int k = 0; k < 16; k++) {
            float a[4];
            #pragma unroll
            for (int i = 0; i < 4; i++) a[i] = As[k][ty * 4 + i];
            float4 b4 = *(float4*)&Bs[k][tx * 4];
            #pragma unroll
            for (int i = 0; i < 4; i++) {
                acc[i][0] = fmaf(a[i], b4.x, acc[i][0]);
                acc[i][1] = fmaf(a[i], b4.y, acc[i][1]);
                acc[i][2] = fmaf(a[i], b4.z, acc[i][2]);
                acc[i][3] = fmaf(a[i], b4.w, acc[i][3]);
            }
        }
        __syncthreads();
    }

    #pragma unroll
    for (int i = 0; i < 4; i++) {
        int gr = m0 + ty * 4 + i;
        if (gr < NN) {
            float4 cv = make_float4(acc[i][0], acc[i][1], acc[i][2], acc[i][3]);
            *(float4*)(g_xw + (size_t)gr * DD + n0 + tx * 4) = cv;
        }
    }
}

// -------- fused gather-aggregate + bias + LayerNorm + ReLU + residual --------
__device__ __forceinline__ float warp_sum(float v) {
    #pragma unroll
    for (int o = 16; o > 0; o >>= 1) v += __shfl_xor_sync(0xffffffffu, v, o);
    return v;
}

__global__ void agg_ln_kernel(const float* __restrict__ bias,
                              const float* __restrict__ gam,
                              const float* __restrict__ bet,
                              float* __restrict__ outp /* may be null */) {
    int warp = (blockIdx.x * blockDim.x + threadIdx.x) >> 5;
    if (warp >= NN) return;
    int lane = threadIdx.x & 31;

    const float4* xw4 = (const float4*)g_xw;
    size_t base4 = (size_t)warp * 64;

    // self-loop: dis^2 * xw[n]
    float s = g_dis[warp]; s = s * s;
    float4 a0 = xw4[base4 + lane];
    float4 a1 = xw4[base4 + 32 + lane];
    a0.x *= s; a0.y *= s; a0.z *= s; a0.w *= s;
    a1.x *= s; a1.y *= s; a1.z *= s; a1.w *= s;

    int off = g_off[warp];
    int cnt = g_cnt[warp];
    int i = 0;
    // unroll-by-2: batch 4 independent 128B gathers before consuming
    for (; i + 2 <= cnt; i += 2) {
        int   rA = g_erow[off + i];
        int   rB = g_erow[off + i + 1];
        float wA = g_enorm[off + i];
        float wB = g_enorm[off + i + 1];
        size_t rbA = (size_t)rA * 64;
        size_t rbB = (size_t)rB * 64;
        float4 vA0 = xw4[rbA + lane];
        float4 vA1 = xw4[rbA + 32 + lane];
        float4 vB0 = xw4[rbB + lane];
        float4 vB1 = xw4[rbB + 32 + lane];
        a0.x = fmaf(wA, vA0.x, a0.x); a0.y = fmaf(wA, vA0.y, a0.y);
        a0.z = fmaf(wA, vA0.z, a0.z); a0.w = fmaf(wA, vA0.w, a0.w);
        a1.x = fmaf(wA, vA1.x, a1.x); a1.y = fmaf(wA, vA1.y, a1.y);
        a1.z = fmaf(wA, vA1.z, a1.z); a1.w = fmaf(wA, vA1.w, a1.w);
        a0.x = fmaf(wB, vB0.x, a0.x); a0.y = fmaf(wB, vB0.y, a0.y);
        a0.z = fmaf(wB, vB0.z, a0.z); a0.w = fmaf(wB, vB0.w, a0.w);
        a1.x = fmaf(wB, vB1.x, a1.x); a1.y = fmaf(wB, vB1.y, a1.y);
        a1.z = fmaf(wB, vB1.z, a1.z); a1.w = fmaf(wB, vB1.w, a1.w);
    }
    for (; i < cnt; i++) {
        int   r = g_erow[off + i];
        float w = g_enorm[off + i];
        size_t rb = (size_t)r * 64;
        float4 v0 = xw4[rb + lane];
        float4 v1 = xw4[rb + 32 + lane];
        a0.x = fmaf(w, v0.x, a0.x); a0.y = fmaf(w, v0.y, a0.y);
        a0.z = fmaf(w, v0.z, a0.z); a0.w = fmaf(w, v0.w, a0.w);
        a1.x = fmaf(w, v1.x, a1.x); a1.y = fmaf(w, v1.y, a1.y);
        a1.z = fmaf(w, v1.z, a1.z); a1.w = fmaf(w, v1.w, a1.w);
    }

    // bias + safe
    const float4* b4 = (const float4*)bias;
    float4 bb0 = b4[lane], bb1 = b4[lane + 32];
    float t[8];
    t[0] = fsafe(a0.x + bb0.x); t[1] = fsafe(a0.y + bb0.y);
    t[2] = fsafe(a0.z + bb0.z); t[3] = fsafe(a0.w + bb0.w);
    t[4] = fsafe(a1.x + bb1.x); t[5] = fsafe(a1.y + bb1.y);
    t[6] = fsafe(a1.z + bb1.z); t[7] = fsafe(a1.w + bb1.w);

    // LayerNorm over 256 via warp reduce
    float ls = t[0] + t[1] + t[2] + t[3] + t[4] + t[5] + t[6] + t[7];
    float mu = warp_sum(ls) * (1.0f / DD);
    float lv = 0.0f;
    #pragma unroll
    for (int j = 0; j < 8; j++) { float d = t[j] - mu; lv = fmaf(d, d, lv); }
    float var = warp_sum(lv) * (1.0f / DD);
    float inv = rsqrtf(var + LN_EPS);

    const float4* g4 = (const float4*)gam;
    const float4* e4 = (const float4*)bet;
    float4 gg0 = g4[lane], gg1 = g4[lane + 32];
    float4 ee0 = e4[lane], ee1 = e4[lane + 32];
    float gv[8] = {gg0.x, gg0.y, gg0.z, gg0.w, gg1.x, gg1.y, gg1.z, gg1.w};
    float ev[8] = {ee0.x, ee0.y, ee0.z, ee0.w, ee1.x, ee1.y, ee1.z, ee1.w};

    // residual source
    float4* h4 = (float4*)g_h;
    float4 r0 = h4[base4 + lane];
    float4 r1 = h4[base4 + 32 + lane];
    float rv[8] = {r0.x, r0.y, r0.z, r0.w, r1.x, r1.y, r1.z, r1.w};

    float o[8];
    #pragma unroll
    for (int j = 0; j < 8; j++) {
        float y = fsafe((t[j] - mu) * inv * gv[j] + ev[j]);
        y = fmaxf(y, 0.0f);               // relu
        o[j] = fsafe(y + rv[j]);          // residual
    }

    float4 w0 = make_float4(o[0], o[1], o[2], o[3]);
    float4 w1 = make_float4(o[4], o[5], o[6], o[7]);
    h4[base4 + lane] = w0;
    h4[base4 + 32 + lane] = w1;
    if (outp) {
        float4* o4 = (float4*)outp;
        o4[base4 + lane] = w0;
        o4[base4 + 32 + lane] = w1;
    }
}

// ---------------------------------------------------------------------------
extern "C" void kernel_launch(void* const* d_in, const int* in_sizes, int n_in,
                              void* d_out, int out_size) {
    const float* x   = (const float*)d_in[0];
    const void*  ei  = d_in[1];                 // [2, E] int64 OR int32
    const float* ew  = (const float*)d_in[2];
    const float* W1  = (const float*)d_in[3];
    const float* b1  = (const float*)d_in[4];
    const float* g1  = (const float*)d_in[5];
    const float* be1 = (const float*)d_in[6];
    const float* W2  = (const float*)d_in[7];
    const float* b2  = (const float*)d_in[8];
    const float* g2  = (const float*)d_in[9];
    const float* be2 = (const float*)d_in[10];
    float* out = (float*)d_out;

    const int T = 256;
    const int edge_blocks = (EE + T - 1) / T;
    const int nd_blocks   = (int)(((size_t)NN * DD + T - 1) / T);
    const int node_blocks = (NN + T - 1) / T;
    dim3 gemm_grid((NN + 63) / 64, DD / 64);
    const int aggr_blocks = (NN * 32 + T - 1) / T;   // one warp per node

    // dtype detection + shared precompute + CSR build
    detect_kernel<<<1, 256>>>((const int*)ei);
    prep_kernel<<<edge_blocks, T>>>(ew);
    deg_kernel<<<edge_blocks, T>>>(ei);
    dis_kernel<<<node_blocks, T>>>();
    scan_kernel<<<node_blocks, T>>>();
    fill_kernel<<<edge_blocks, T>>>(ei);
    copyx_kernel<<<nd_blocks, T>>>(x);

    // ---- layer 1 ----
    sgemm_kernel<<<gemm_grid, T>>>(W1);
    agg_ln_kernel<<<aggr_blocks, T>>>(b1, g1, be1, nullptr);

    // ---- layer 2 ----
    sgemm_kernel<<<gemm_grid, T>>>(W2);
    agg_ln_kernel<<<aggr_blocks, T>>>(b2, g2, be2, out);
}

// round 5
// speedup vs baseline: 1.3779x; 1.3779x over previous
#include <cuda_runtime.h>
#include <cstdint>

#define NN 100000
#define DD 256
#define EE 3200000
#define LN_EPS 1e-5f

// -------- scratch (static device globals; no runtime allocation) --------
__device__ __align__(16) float g_h   [(size_t)NN * DD];   // current features
__device__ __align__(16) float g_xw  [(size_t)NN * DD];   // h @ W
__device__ float g_deg [NN];
__device__ float g_dis [NN];
__device__ float g_ew  [EE];
__device__ int   g_cnt [NN];                // in-degree per dst
__device__ int   g_off [NN];                // CSR segment start per dst
__device__ int   g_cur [NN];                // fill cursor per dst
__device__ int   g_erow [EE];               // CSR: source node per slot
__device__ float g_enorm[EE];               // CSR: edge norm per slot
__device__ int   g_total;                   // base for segment placement
__device__ int   g_is64;                    // edge_index dtype flag

// fast-math-safe finite check (bit pattern, cannot be folded away)
__device__ __forceinline__ float fsafe(float v) {
    unsigned u = __float_as_uint(v);
    return ((u & 0x7f800000u) == 0x7f800000u) ? 0.0f : v;
}

// -------- dtype detection: int64 vs int32 edge_index --------
__global__ void detect_kernel(const int* __restrict__ ei32) {
    __shared__ int cnt;
    if (threadIdx.x == 0) cnt = 0;
    __syncthreads();
    int nz = 0;
    for (int k = threadIdx.x; k < 2048; k += blockDim.x) {
        if (ei32[2 * k + 1] != 0) nz++;                      // window 1: start
        if (ei32[2 * (EE / 2 + k) + 1] != 0) nz++;           // window 2: middle
    }
    atomicAdd(&cnt, nz);
    __syncthreads();
    if (threadIdx.x == 0) g_is64 = (cnt < 2048) ? 1 : 0;
}

__device__ __forceinline__ int load_idx(const void* ei, size_t pos, int is64) {
    if (is64) return (int)((const long long*)ei)[pos];
    return ((const int*)ei)[pos];
}

// -------- prep: safe edge weights + zero counters --------
__global__ void prep_kernel(const float* __restrict__ ew_in) {
    int i = blockIdx.x * blockDim.x + threadIdx.x;
    if (i < EE) g_ew[i] = fmaxf(fabsf(fsafe(ew_in[i])), 1e-6f);
    if (i < NN) { g_deg[i] = 0.0f; g_cnt[i] = 0; g_cur[i] = 0; }
    if (i == 0) g_total = 0;
}

// -------- degree + count accumulation over dst (col) --------
__global__ void deg_kernel(const void* __restrict__ ei) {
    int e = blockIdx.x * blockDim.x + threadIdx.x;
    if (e >= EE) return;
    int is64 = g_is64;
    int c = load_idx(ei, (size_t)EE + e, is64);
    if ((unsigned)c < NN) {
        atomicAdd(&g_deg[c], g_ew[e]);
        atomicAdd(&g_cnt[c], 1);
    }
}

// -------- dis = rsqrt(deg + 1) --------
__global__ void dis_kernel() {
    int i = blockIdx.x * blockDim.x + threadIdx.x;
    if (i < NN) g_dis[i] = rsqrtf(g_deg[i] + 1.0f);
}

// -------- segment placement: per-block scan + one atomic per block --------
__global__ void scan_kernel() {
    __shared__ int warp_tot[8];
    __shared__ int blk_base;
    int n = blockIdx.x * 256 + threadIdx.x;
    int lane = threadIdx.x & 31, w = threadIdx.x >> 5;

    int c = (n < NN) ? g_cnt[n] : 0;
    int incl = c;
    #pragma unroll
    for (int o = 1; o < 32; o <<= 1) {
        int t = __shfl_up_sync(0xffffffffu, incl, o);
        if (lane >= o) incl += t;
    }
    if (lane == 31) warp_tot[w] = incl;
    __syncthreads();
    if (w == 0) {
        int t = (lane < 8) ? warp_tot[lane] : 0;
        #pragma unroll
        for (int o = 1; o < 8; o <<= 1) {
            int u = __shfl_up_sync(0xffffffffu, t, o);
            if (lane >= o) t += u;
        }
        if (lane < 8) warp_tot[lane] = t;
        if (lane == 7) blk_base = atomicAdd(&g_total, t);
    }
    __syncthreads();
    int prefix = blk_base + (w > 0 ? warp_tot[w - 1] : 0) + incl - c;
    if (n < NN) g_off[n] = prefix;
}

// -------- CSR fill: place (row, norm) into dst segment --------
__global__ void fill_kernel(const void* __restrict__ ei) {
    int e = blockIdx.x * blockDim.x + threadIdx.x;
    if (e >= EE) return;
    int is64 = g_is64;
    int r = load_idx(ei, (size_t)e, is64);
    int c = load_idx(ei, (size_t)EE + e, is64);
    if ((unsigned)r >= NN || (unsigned)c >= NN) return;
    float norm = g_dis[r] * g_ew[e] * g_dis[c];
    int p = atomicAdd(&g_cur[c], 1);
    int slot = g_off[c] + p;
    if ((unsigned)slot < EE) {
        g_erow[slot]  = r;
        g_enorm[slot] = norm;
    }
}

// -------- h = safe(x) --------
__global__ void copyx_kernel(const float* __restrict__ x) {
    size_t i = (size_t)blockIdx.x * blockDim.x + threadIdx.x;
    if (i < (size_t)NN * DD) g_h[i] = fsafe(x[i]);
}

// ============ tf32 tensor-core GEMM: g_xw = g_h @ W ============
// M=NN, N=256, K=256.  Block tile 128x128, BK=32, 256 threads (8 warps).
// Warp grid 4(M) x 2(N): warp tile 32x64 = 2(m16) x 8(n8) mma.m16n8k8.

__device__ __forceinline__ uint32_t tf32r(float f) {
    uint32_t r;
    asm("cvt.rna.tf32.f32 %0, %1;" : "=r"(r) : "f"(f));
    return r;
}

__device__ __forceinline__ void mma_tf32(float* c,
                                         uint32_t a0, uint32_t a1,
                                         uint32_t a2, uint32_t a3,
                                         uint32_t b0, uint32_t b1) {
    asm volatile(
        "mma.sync.aligned.m16n8k8.row.col.f32.tf32.tf32.f32 "
        "{%0,%1,%2,%3}, {%4,%5,%6,%7}, {%8,%9}, {%0,%1,%2,%3};"
        : "+f"(c[0]), "+f"(c[1]), "+f"(c[2]), "+f"(c[3])
        : "r"(a0), "r"(a1), "r"(a2), "r"(a3), "r"(b0), "r"(b1));
}

__global__ __launch_bounds__(256) void tf32gemm_kernel(const float* __restrict__ W) {
    __shared__ uint32_t As[32][132];   // k-major A (transposed), +4 pad
    __shared__ uint32_t Bs[32][132];   // k-major B, +4 pad

    const int tid  = threadIdx.x;
    const int wid  = tid >> 5;
    const int lane = tid & 31;
    const int wm   = wid & 3;          // 0..3 -> M direction
    const int wn   = wid >> 2;         // 0..1 -> N direction
    const int m0   = blockIdx.x * 128;
    const int n0   = blockIdx.y * 128;

    const int lr = lane >> 2;          // 0..7
    const int lc = lane & 3;           // 0..3

    // staging indices
    const int arow = tid >> 1;         // 0..127 (A row within tile)
    const int ac4  = (tid & 1) * 4;    // float4 index base within 32-k row
    const int bk   = tid >> 3;         // 0..31 (B k-row)
    const int bc0  = tid & 7;          // 0..7, steps of 8 -> covers 0..31

    float acc[2][8][4] = {};

    for (int k0 = 0; k0 < DD; k0 += 32) {
        // ---- stage A (transpose to k-major, cvt to tf32) ----
        int grow = m0 + arow;
        #pragma unroll
        for (int i = 0; i < 4; i++) {
            int c4 = ac4 + i;          // 0..7
            float4 v = make_float4(0.f, 0.f, 0.f, 0.f);
            if (grow < NN)
                v = *(const float4*)(g_h + (size_t)grow * DD + k0 + c4 * 4);
            As[c4 * 4 + 0][arow] = tf32r(v.x);
            As[c4 * 4 + 1][arow] = tf32r(v.y);
            As[c4 * 4 + 2][arow] = tf32r(v.z);
            As[c4 * 4 + 3][arow] = tf32r(v.w);
        }
        // ---- stage B (direct, cvt to tf32) ----
        #pragma unroll
        for (int i = 0; i < 4; i++) {
            int c4 = bc0 + i * 8;      // 0..31
            float4 v = *(const float4*)(W + (size_t)(k0 + bk) * DD + n0 + c4 * 4);
            uint4 u;
            u.x = tf32r(v.x); u.y = tf32r(v.y);
            u.z = tf32r(v.z); u.w = tf32r(v.w);
            *(uint4*)&Bs[bk][c4 * 4] = u;
        }
        __syncthreads();

        // ---- compute: 4 k8-steps ----
        #pragma unroll
        for (int k8 = 0; k8 < 32; k8 += 8) {
            uint32_t b[8][2];
            #pragma unroll
            for (int nt = 0; nt < 8; nt++) {
                int ncol = wn * 64 + nt * 8 + lr;
                b[nt][0] = Bs[k8 + lc][ncol];
                b[nt][1] = Bs[k8 + 4 + lc][ncol];
            }
            #pragma unroll
            for (int mt = 0; mt < 2; mt++) {
                int mrow = wm * 32 + mt * 16 + lr;
                uint32_t a0 = As[k8 + lc][mrow];
                uint32_t a1 = As[k8 + lc][mrow + 8];
                uint32_t a2 = As[k8 + 4 + lc][mrow];
                uint32_t a3 = As[k8 + 4 + lc][mrow + 8];
                #pragma unroll
                for (int nt = 0; nt < 8; nt++)
                    mma_tf32(acc[mt][nt], a0, a1, a2, a3, b[nt][0], b[nt][1]);
            }
        }
        __syncthreads();
    }

    // ---- epilogue: float2 stores ----
    #pragma unroll
    for (int mt = 0; mt < 2; mt++) {
        int r0 = m0 + wm * 32 + mt * 16 + lr;
        #pragma unroll
        for (int nt = 0; nt < 8; nt++) {
            int c = n0 + wn * 64 + nt * 8 + lc * 2;
            if (r0 < NN)
                *(float2*)(g_xw + (size_t)r0 * DD + c) =
                    make_float2(acc[mt][nt][0], acc[mt][nt][1]);
            if (r0 + 8 < NN)
                *(float2*)(g_xw + (size_t)(r0 + 8) * DD + c) =
                    make_float2(acc[mt][nt][2], acc[mt][nt][3]);
        }
    }
}

// -------- fused gather-aggregate + bias + LayerNorm + ReLU + residual --------
__device__ __forceinline__ float warp_sum(float v) {
    #pragma unroll
    for (int o = 16; o > 0; o >>= 1) v += __shfl_xor_sync(0xffffffffu, v, o);
    return v;
}

__global__ void agg_ln_kernel(const float* __restrict__ bias,
                              const float* __restrict__ gam,
                              const float* __restrict__ bet,
                              float* __restrict__ outp /* may be null */) {
    int warp = (blockIdx.x * blockDim.x + threadIdx.x) >> 5;
    if (warp >= NN) return;
    int lane = threadIdx.x & 31;

    const float4* xw4 = (const float4*)g_xw;
    size_t base4 = (size_t)warp * 64;

    // self-loop: dis^2 * xw[n]
    float s = g_dis[warp]; s = s * s;
    float4 a0 = xw4[base4 + lane];
    float4 a1 = xw4[base4 + 32 + lane];
    a0.x *= s; a0.y *= s; a0.z *= s; a0.w *= s;
    a1.x *= s; a1.y *= s; a1.z *= s; a1.w *= s;

    int off = g_off[warp];
    int cnt = g_cnt[warp];
    int i = 0;
    for (; i + 2 <= cnt; i += 2) {
        int   rA = g_erow[off + i];
        int   rB = g_erow[off + i + 1];
        float wA = g_enorm[off + i];
        float wB = g_enorm[off + i + 1];
        size_t rbA = (size_t)rA * 64;
        size_t rbB = (size_t)rB * 64;
        float4 vA0 = xw4[rbA + lane];
        float4 vA1 = xw4[rbA + 32 + lane];
        float4 vB0 = xw4[rbB + lane];
        float4 vB1 = xw4[rbB + 32 + lane];
        a0.x = fmaf(wA, vA0.x, a0.x); a0.y = fmaf(wA, vA0.y, a0.y);
        a0.z = fmaf(wA, vA0.z, a0.z); a0.w = fmaf(wA, vA0.w, a0.w);
        a1.x = fmaf(wA, vA1.x, a1.x); a1.y = fmaf(wA, vA1.y, a1.y);
        a1.z = fmaf(wA, vA1.z, a1.z); a1.w = fmaf(wA, vA1.w, a1.w);
        a0.x = fmaf(wB, vB0.x, a0.x); a0.y = fmaf(wB, vB0.y, a0.y);
        a0.z = fmaf(wB, vB0.z, a0.z); a0.w = fmaf(wB, vB0.w, a0.w);
        a1.x = fmaf(wB, vB1.x, a1.x); a1.y = fmaf(wB, vB1.y, a1.y);
        a1.z = fmaf(wB, vB1.z, a1.z); a1.w = fmaf(wB, vB1.w, a1.w);
    }
    for (; i < cnt; i++) {
        int   r = g_erow[off + i];
        float w = g_enorm[off + i];
        size_t rb = (size_t)r * 64;
        float4 v0 = xw4[rb + lane];
        float4 v1 = xw4[rb + 32 + lane];
        a0.x = fmaf(w, v0.x, a0.x); a0.y = fmaf(w, v0.y, a0.y);
        a0.z = fmaf(w, v0.z, a0.z); a0.w = fmaf(w, v0.w, a0.w);
        a1.x = fmaf(w, v1.x, a1.x); a1.y = fmaf(w, v1.y, a1.y);
        a1.z = fmaf(w, v1.z, a1.z); a1.w = fmaf(w, v1.w, a1.w);
    }

    // bias + safe
    const float4* b4 = (const float4*)bias;
    float4 bb0 = b4[lane], bb1 = b4[lane + 32];
    float t[8];
    t[0] = fsafe(a0.x + bb0.x); t[1] = fsafe(a0.y + bb0.y);
    t[2] = fsafe(a0.z + bb0.z); t[3] = fsafe(a0.w + bb0.w);
    t[4] = fsafe(a1.x + bb1.x); t[5] = fsafe(a1.y + bb1.y);
    t[6] = fsafe(a1.z + bb1.z); t[7] = fsafe(a1.w + bb1.w);

    // LayerNorm over 256 via warp reduce
    float ls = t[0] + t[1] + t[2] + t[3] + t[4] + t[5] + t[6] + t[7];
    float mu = warp_sum(ls) * (1.0f / DD);
    float lv = 0.0f;
    #pragma unroll
    for (int j = 0; j < 8; j++) { float d = t[j] - mu; lv = fmaf(d, d, lv); }
    float var = warp_sum(lv) * (1.0f / DD);
    float inv = rsqrtf(var + LN_EPS);

    const float4* g4 = (const float4*)gam;
    const float4* e4 = (const float4*)bet;
    float4 gg0 = g4[lane], gg1 = g4[lane + 32];
    float4 ee0 = e4[lane], ee1 = e4[lane + 32];
    float gv[8] = {gg0.x, gg0.y, gg0.z, gg0.w, gg1.x, gg1.y, gg1.z, gg1.w};
    float ev[8] = {ee0.x, ee0.y, ee0.z, ee0.w, ee1.x, ee1.y, ee1.z, ee1.w};

    // residual source
    float4* h4 = (float4*)g_h;
    float4 r0 = h4[base4 + lane];
    float4 r1 = h4[base4 + 32 + lane];
    float rv[8] = {r0.x, r0.y, r0.z, r0.w, r1.x, r1.y, r1.z, r1.w};

    float o[8];
    #pragma unroll
    for (int j = 0; j < 8; j++) {
        float y = fsafe((t[j] - mu) * inv * gv[j] + ev[j]);
        y = fmaxf(y, 0.0f);               // relu
        o[j] = fsafe(y + rv[j]);          // residual
    }

    float4 w0 = make_float4(o[0], o[1], o[2], o[3]);
    float4 w1 = make_float4(o[4], o[5], o[6], o[7]);
    h4[base4 + lane] = w0;
    h4[base4 + 32 + lane] = w1;
    if (outp) {
        float4* o4 = (float4*)outp;
        o4[base4 + lane] = w0;
        o4[base4 + 32 + lane] = w1;
    }
}

// ---------------------------------------------------------------------------
extern "C" void kernel_launch(void* const* d_in, const int* in_sizes, int n_in,
                              void* d_out, int out_size) {
    const float* x   = (const float*)d_in[0];
    const void*  ei  = d_in[1];                 // [2, E] int64 OR int32
    const float* ew  = (const float*)d_in[2];
    const float* W1  = (const float*)d_in[3];
    const float* b1  = (const float*)d_in[4];
    const float* g1  = (const float*)d_in[5];
    const float* be1 = (const float*)d_in[6];
    const float* W2  = (const float*)d_in[7];
    const float* b2  = (const float*)d_in[8];
    const float* g2  = (const float*)d_in[9];
    const float* be2 = (const float*)d_in[10];
    float* out = (float*)d_out;

    const int T = 256;
    const int edge_blocks = (EE + T - 1) / T;
    const int nd_blocks   = (int)(((size_t)NN * DD + T - 1) / T);
    const int node_blocks = (NN + T - 1) / T;
    dim3 gemm_grid((NN + 127) / 128, DD / 128);
    const int aggr_blocks = (NN * 32 + T - 1) / T;   // one warp per node

    // dtype detection + shared precompute + CSR build
    detect_kernel<<<1, 256>>>((const int*)ei);
    prep_kernel<<<edge_blocks, T>>>(ew);
    deg_kernel<<<edge_blocks, T>>>(ei);
    dis_kernel<<<node_blocks, T>>>();
    scan_kernel<<<node_blocks, T>>>();
    fill_kernel<<<edge_blocks, T>>>(ei);
    copyx_kernel<<<nd_blocks, T>>>(x);

    // ---- layer 1 ----
    tf32gemm_kernel<<<gemm_grid, T>>>(W1);
    agg_ln_kernel<<<aggr_blocks, T>>>(b1, g1, be1, nullptr);

    // ---- layer 2 ----
    tf32gemm_kernel<<<gemm_grid, T>>>(W2);
    agg_ln_kernel<<<aggr_blocks, T>>>(b2, g2, be2, out);
}

// round 6
// speedup vs baseline: 1.6930x; 1.2287x over previous
#include <cuda_runtime.h>
#include <cuda_fp16.h>
#include <cstdint>

#define NN 100000
#define DD 256
#define EE 3200000
#define LN_EPS 1e-5f

// -------- scratch (static device globals; no runtime allocation) --------
__device__ __align__(16) float  g_h   [(size_t)NN * DD];   // current features (fp32)
__device__ __align__(16) __half g_xwh [(size_t)NN * DD];   // h @ W in fp16 (51.2 MB)
__device__ float g_deg [NN];
__device__ float g_dis [NN];
__device__ float g_ew  [EE];
__device__ int   g_cnt [NN];                // in-degree per dst
__device__ int   g_off [NN];                // CSR segment start per dst
__device__ int   g_cur [NN];                // fill cursor per dst
__device__ int   g_erow [EE];               // CSR: source node per slot
__device__ float g_enorm[EE];               // CSR: edge norm per slot
__device__ int   g_total;                   // base for segment placement
__device__ int   g_is64;                    // edge_index dtype flag

// fast-math-safe finite check (bit pattern, cannot be folded away)
__device__ __forceinline__ float fsafe(float v) {
    unsigned u = __float_as_uint(v);
    return ((u & 0x7f800000u) == 0x7f800000u) ? 0.0f : v;
}

// -------- dtype detection: int64 vs int32 edge_index --------
__global__ void detect_kernel(const int* __restrict__ ei32) {
    __shared__ int cnt;
    if (threadIdx.x == 0) cnt = 0;
    __syncthreads();
    int nz = 0;
    for (int k = threadIdx.x; k < 2048; k += blockDim.x) {
        if (ei32[2 * k + 1] != 0) nz++;
        if (ei32[2 * (EE / 2 + k) + 1] != 0) nz++;
    }
    atomicAdd(&cnt, nz);
    __syncthreads();
    if (threadIdx.x == 0) g_is64 = (cnt < 2048) ? 1 : 0;
}

__device__ __forceinline__ int load_idx(const void* ei, size_t pos, int is64) {
    if (is64) return (int)((const long long*)ei)[pos];
    return ((const int*)ei)[pos];
}

// -------- prep: safe edge weights + zero counters --------
__global__ void prep_kernel(const float* __restrict__ ew_in) {
    int i = blockIdx.x * blockDim.x + threadIdx.x;
    if (i < EE) g_ew[i] = fmaxf(fabsf(fsafe(ew_in[i])), 1e-6f);
    if (i < NN) { g_deg[i] = 0.0f; g_cnt[i] = 0; g_cur[i] = 0; }
    if (i == 0) g_total = 0;
}

// -------- degree + count accumulation over dst (col) --------
__global__ void deg_kernel(const void* __restrict__ ei) {
    int e = blockIdx.x * blockDim.x + threadIdx.x;
    if (e >= EE) return;
    int is64 = g_is64;
    int c = load_idx(ei, (size_t)EE + e, is64);
    if ((unsigned)c < NN) {
        atomicAdd(&g_deg[c], g_ew[e]);
        atomicAdd(&g_cnt[c], 1);
    }
}

// -------- dis = rsqrt(deg + 1) --------
__global__ void dis_kernel() {
    int i = blockIdx.x * blockDim.x + threadIdx.x;
    if (i < NN) g_dis[i] = rsqrtf(g_deg[i] + 1.0f);
}

// -------- segment placement: per-block scan + one atomic per block --------
__global__ void scan_kernel() {
    __shared__ int warp_tot[8];
    __shared__ int blk_base;
    int n = blockIdx.x * 256 + threadIdx.x;
    int lane = threadIdx.x & 31, w = threadIdx.x >> 5;

    int c = (n < NN) ? g_cnt[n] : 0;
    int incl = c;
    #pragma unroll
    for (int o = 1; o < 32; o <<= 1) {
        int t = __shfl_up_sync(0xffffffffu, incl, o);
        if (lane >= o) incl += t;
    }
    if (lane == 31) warp_tot[w] = incl;
    __syncthreads();
    if (w == 0) {
        int t = (lane < 8) ? warp_tot[lane] : 0;
        #pragma unroll
        for (int o = 1; o < 8; o <<= 1) {
            int u = __shfl_up_sync(0xffffffffu, t, o);
            if (lane >= o) t += u;
        }
        if (lane < 8) warp_tot[lane] = t;
        if (lane == 7) blk_base = atomicAdd(&g_total, t);
    }
    __syncthreads();
    int prefix = blk_base + (w > 0 ? warp_tot[w - 1] : 0) + incl - c;
    if (n < NN) g_off[n] = prefix;
}

// -------- CSR fill: place (row, norm) into dst segment --------
__global__ void fill_kernel(const void* __restrict__ ei) {
    int e = blockIdx.x * blockDim.x + threadIdx.x;
    if (e >= EE) return;
    int is64 = g_is64;
    int r = load_idx(ei, (size_t)e, is64);
    int c = load_idx(ei, (size_t)EE + e, is64);
    if ((unsigned)r >= NN || (unsigned)c >= NN) return;
    float norm = g_dis[r] * g_ew[e] * g_dis[c];
    int p = atomicAdd(&g_cur[c], 1);
    int slot = g_off[c] + p;
    if ((unsigned)slot < EE) {
        g_erow[slot]  = r;
        g_enorm[slot] = norm;
    }
}

// -------- h = safe(x) --------
__global__ void copyx_kernel(const float* __restrict__ x) {
    size_t i = (size_t)blockIdx.x * blockDim.x + threadIdx.x;
    if (i < (size_t)NN * DD) g_h[i] = fsafe(x[i]);
}

// ============ tf32 tensor-core GEMM: g_xwh = half(g_h @ W) ============
__device__ __forceinline__ uint32_t tf32r(float f) {
    uint32_t r;
    asm("cvt.rna.tf32.f32 %0, %1;" : "=r"(r) : "f"(f));
    return r;
}

__device__ __forceinline__ void mma_tf32(float* c,
                                         uint32_t a0, uint32_t a1,
                                         uint32_t a2, uint32_t a3,
                                         uint32_t b0, uint32_t b1) {
    asm volatile(
        "mma.sync.aligned.m16n8k8.row.col.f32.tf32.tf32.f32 "
        "{%0,%1,%2,%3}, {%4,%5,%6,%7}, {%8,%9}, {%0,%1,%2,%3};"
        : "+f"(c[0]), "+f"(c[1]), "+f"(c[2]), "+f"(c[3])
        : "r"(a0), "r"(a1), "r"(a2), "r"(a3), "r"(b0), "r"(b1));
}

__global__ __launch_bounds__(256) void tf32gemm_kernel(const float* __restrict__ W) {
    __shared__ uint32_t As[32][132];
    __shared__ uint32_t Bs[32][132];

    const int tid  = threadIdx.x;
    const int wid  = tid >> 5;
    const int lane = tid & 31;
    const int wm   = wid & 3;
    const int wn   = wid >> 2;
    const int m0   = blockIdx.x * 128;
    const int n0   = blockIdx.y * 128;

    const int lr = lane >> 2;
    const int lc = lane & 3;

    const int arow = tid >> 1;
    const int ac4  = (tid & 1) * 4;
    const int bk   = tid >> 3;
    const int bc0  = tid & 7;

    float acc[2][8][4] = {};

    for (int k0 = 0; k0 < DD; k0 += 32) {
        int grow = m0 + arow;
        #pragma unroll
        for (int i = 0; i < 4; i++) {
            int c4 = ac4 + i;
            float4 v = make_float4(0.f, 0.f, 0.f, 0.f);
            if (grow < NN)
                v = *(const float4*)(g_h + (size_t)grow * DD + k0 + c4 * 4);
            As[c4 * 4 + 0][arow] = tf32r(v.x);
            As[c4 * 4 + 1][arow] = tf32r(v.y);
            As[c4 * 4 + 2][arow] = tf32r(v.z);
            As[c4 * 4 + 3][arow] = tf32r(v.w);
        }
        #pragma unroll
        for (int i = 0; i < 4; i++) {
            int c4 = bc0 + i * 8;
            float4 v = *(const float4*)(W + (size_t)(k0 + bk) * DD + n0 + c4 * 4);
            uint4 u;
            u.x = tf32r(v.x); u.y = tf32r(v.y);
            u.z = tf32r(v.z); u.w = tf32r(v.w);
            *(uint4*)&Bs[bk][c4 * 4] = u;
        }
        __syncthreads();

        #pragma unroll
        for (int k8 = 0; k8 < 32; k8 += 8) {
            uint32_t b[8][2];
            #pragma unroll
            for (int nt = 0; nt < 8; nt++) {
                int ncol = wn * 64 + nt * 8 + lr;
                b[nt][0] = Bs[k8 + lc][ncol];
                b[nt][1] = Bs[k8 + 4 + lc][ncol];
            }
            #pragma unroll
            for (int mt = 0; mt < 2; mt++) {
                int mrow = wm * 32 + mt * 16 + lr;
                uint32_t a0 = As[k8 + lc][mrow];
                uint32_t a1 = As[k8 + lc][mrow + 8];
                uint32_t a2 = As[k8 + 4 + lc][mrow];
                uint32_t a3 = As[k8 + 4 + lc][mrow + 8];
                #pragma unroll
                for (int nt = 0; nt < 8; nt++)
                    mma_tf32(acc[mt][nt], a0, a1, a2, a3, b[nt][0], b[nt][1]);
            }
        }
        __syncthreads();
    }

    // epilogue: half2 stores
    #pragma unroll
    for (int mt = 0; mt < 2; mt++) {
        int r0 = m0 + wm * 32 + mt * 16 + lr;
        #pragma unroll
        for (int nt = 0; nt < 8; nt++) {
            int c = n0 + wn * 64 + nt * 8 + lc * 2;
            if (r0 < NN)
                *(__half2*)(g_xwh + (size_t)r0 * DD + c) =
                    __floats2half2_rn(acc[mt][nt][0], acc[mt][nt][1]);
            if (r0 + 8 < NN)
                *(__half2*)(g_xwh + (size_t)(r0 + 8) * DD + c) =
                    __floats2half2_rn(acc[mt][nt][2], acc[mt][nt][3]);
        }
    }
}

// -------- fused gather-aggregate + bias + LayerNorm + ReLU + residual --------
__device__ __forceinline__ float warp_sum(float v) {
    #pragma unroll
    for (int o = 16; o > 0; o >>= 1) v += __shfl_xor_sync(0xffffffffu, v, o);
    return v;
}

__device__ __forceinline__ void fma8(float* a, float w, uint4 u) {
    __half2* h = (__half2*)&u;
    float2 p0 = __half22float2(h[0]);
    float2 p1 = __half22float2(h[1]);
    float2 p2 = __half22float2(h[2]);
    float2 p3 = __half22float2(h[3]);
    a[0] = fmaf(w, p0.x, a[0]); a[1] = fmaf(w, p0.y, a[1]);
    a[2] = fmaf(w, p1.x, a[2]); a[3] = fmaf(w, p1.y, a[3]);
    a[4] = fmaf(w, p2.x, a[4]); a[5] = fmaf(w, p2.y, a[5]);
    a[6] = fmaf(w, p3.x, a[6]); a[7] = fmaf(w, p3.y, a[7]);
}

__global__ void agg_ln_kernel(const float* __restrict__ bias,
                              const float* __restrict__ gam,
                              const float* __restrict__ bet,
                              float* __restrict__ outp /* may be null */) {
    int warp = (blockIdx.x * blockDim.x + threadIdx.x) >> 5;
    if (warp >= NN) return;
    int lane = threadIdx.x & 31;

    // each lane owns 8 consecutive dims: [lane*8, lane*8+8)
    const uint4* xwv = (const uint4*)g_xwh;    // 8 halves per uint4; 32 per row
    size_t base = (size_t)warp * 32;

    float a[8] = {};
    // self-loop: dis^2 * xw[n]
    float s = g_dis[warp]; s = s * s;
    fma8(a, s, xwv[base + lane]);

    int off = g_off[warp];
    int cnt = g_cnt[warp];
    int i = 0;
    for (; i + 4 <= cnt; i += 4) {
        int   r0 = g_erow[off + i];
        int   r1 = g_erow[off + i + 1];
        int   r2 = g_erow[off + i + 2];
        int   r3 = g_erow[off + i + 3];
        float w0 = g_enorm[off + i];
        float w1 = g_enorm[off + i + 1];
        float w2 = g_enorm[off + i + 2];
        float w3 = g_enorm[off + i + 3];
        uint4 u0 = xwv[(size_t)r0 * 32 + lane];
        uint4 u1 = xwv[(size_t)r1 * 32 + lane];
        uint4 u2 = xwv[(size_t)r2 * 32 + lane];
        uint4 u3 = xwv[(size_t)r3 * 32 + lane];
        fma8(a, w0, u0);
        fma8(a, w1, u1);
        fma8(a, w2, u2);
        fma8(a, w3, u3);
    }
    for (; i < cnt; i++) {
        int   r = g_erow[off + i];
        float w = g_enorm[off + i];
        fma8(a, w, xwv[(size_t)r * 32 + lane]);
    }

    // bias + safe  (dims lane*8 + j)
    const float4* b4 = (const float4*)bias;
    float4 bb0 = b4[lane * 2], bb1 = b4[lane * 2 + 1];
    float t[8];
    t[0] = fsafe(a[0] + bb0.x); t[1] = fsafe(a[1] + bb0.y);
    t[2] = fsafe(a[2] + bb0.z); t[3] = fsafe(a[3] + bb0.w);
    t[4] = fsafe(a[4] + bb1.x); t[5] = fsafe(a[5] + bb1.y);
    t[6] = fsafe(a[6] + bb1.z); t[7] = fsafe(a[7] + bb1.w);

    // LayerNorm over 256 via warp reduce
    float ls = t[0] + t[1] + t[2] + t[3] + t[4] + t[5] + t[6] + t[7];
    float mu = warp_sum(ls) * (1.0f / DD);
    float lv = 0.0f;
    #pragma unroll
    for (int j = 0; j < 8; j++) { float d = t[j] - mu; lv = fmaf(d, d, lv); }
    float var = warp_sum(lv) * (1.0f / DD);
    float inv = rsqrtf(var + LN_EPS);

    const float4* g4 = (const float4*)gam;
    const float4* e4 = (const float4*)bet;
    float4 gg0 = g4[lane * 2], gg1 = g4[lane * 2 + 1];
    float4 ee0 = e4[lane * 2], ee1 = e4[lane * 2 + 1];
    float gv[8] = {gg0.x, gg0.y, gg0.z, gg0.w, gg1.x, gg1.y, gg1.z, gg1.w};
    float ev[8] = {ee0.x, ee0.y, ee0.z, ee0.w, ee1.x, ee1.y, ee1.z, ee1.w};

    // residual source (fp32 h)
    float4* h4 = (float4*)g_h;
    size_t hbase = (size_t)warp * 64 + lane * 2;
    float4 r0 = h4[hbase], r1 = h4[hbase + 1];
    float rv[8] = {r0.x, r0.y, r0.z, r0.w, r1.x, r1.y, r1.z, r1.w};

    float o[8];
    #pragma unroll
    for (int j = 0; j < 8; j++) {
        float y = fsafe((t[j] - mu) * inv * gv[j] + ev[j]);
        y = fmaxf(y, 0.0f);               // relu
        o[j] = fsafe(y + rv[j]);          // residual
    }

    float4 w0 = make_float4(o[0], o[1], o[2], o[3]);
    float4 w1 = make_float4(o[4], o[5], o[6], o[7]);
    h4[hbase] = w0;
    h4[hbase + 1] = w1;
    if (outp) {
        float4* o4 = (float4*)outp;
        o4[hbase] = w0;
        o4[hbase + 1] = w1;
    }
}

// ---------------------------------------------------------------------------
extern "C" void kernel_launch(void* const* d_in, const int* in_sizes, int n_in,
                              void* d_out, int out_size) {
    const float* x   = (const float*)d_in[0];
    const void*  ei  = d_in[1];                 // [2, E] int64 OR int32
    const float* ew  = (const float*)d_in[2];
    const float* W1  = (const float*)d_in[3];
    const float* b1  = (const float*)d_in[4];
    const float* g1  = (const float*)d_in[5];
    const float* be1 = (const float*)d_in[6];
    const float* W2  = (const float*)d_in[7];
    const float* b2  = (const float*)d_in[8];
    const float* g2  = (const float*)d_in[9];
    const float* be2 = (const float*)d_in[10];
    float* out = (float*)d_out;

    const int T = 256;
    const int edge_blocks = (EE + T - 1) / T;
    const int nd_blocks   = (int)(((size_t)NN * DD + T - 1) / T);
    const int node_blocks = (NN + T - 1) / T;
    dim3 gemm_grid((NN + 127) / 128, DD / 128);
    const int aggr_blocks = (NN * 32 + T - 1) / T;   // one warp per node

    // dtype detection + shared precompute + CSR build
    detect_kernel<<<1, 256>>>((const int*)ei);
    prep_kernel<<<edge_blocks, T>>>(ew);
    deg_kernel<<<edge_blocks, T>>>(ei);
    dis_kernel<<<node_blocks, T>>>();
    scan_kernel<<<node_blocks, T>>>();
    fill_kernel<<<edge_blocks, T>>>(ei);
    copyx_kernel<<<nd_blocks, T>>>(x);

    // ---- layer 1 ----
    tf32gemm_kernel<<<gemm_grid, T>>>(W1);
    agg_ln_kernel<<<aggr_blocks, T>>>(b1, g1, be1, nullptr);

    // ---- layer 2 ----
    tf32gemm_kernel<<<gemm_grid, T>>>(W2);
    agg_ln_kernel<<<aggr_blocks, T>>>(b2, g2, be2, out);
}

// round 7
// speedup vs baseline: 1.7937x; 1.0595x over previous
#include <cuda_runtime.h>
#include <cuda_fp16.h>
#include <cstdint>

#define NN 100000
#define DD 256
#define EE 3200000
#define LN_EPS 1e-5f

// -------- scratch (static device globals; no runtime allocation) --------
__device__ __align__(16) float  g_h   [(size_t)NN * DD];   // current features (fp32)
__device__ __align__(16) __half g_xwh [(size_t)NN * DD];   // h @ W in fp16 (51.2 MB)
__device__ float g_deg [NN];
__device__ float g_dis [NN];
__device__ float g_ew  [EE];
__device__ int   g_cnt [NN];
__device__ int   g_off [NN];
__device__ int   g_cur [NN];
__device__ int   g_erow [EE];
__device__ float g_enorm[EE];
__device__ int   g_total;
__device__ int   g_is64;

__device__ __forceinline__ float fsafe(float v) {
    unsigned u = __float_as_uint(v);
    return ((u & 0x7f800000u) == 0x7f800000u) ? 0.0f : v;
}

// -------- dtype detection: int64 vs int32 edge_index --------
__global__ void detect_kernel(const int* __restrict__ ei32) {
    __shared__ int cnt;
    if (threadIdx.x == 0) cnt = 0;
    __syncthreads();
    int nz = 0;
    for (int k = threadIdx.x; k < 2048; k += blockDim.x) {
        if (ei32[2 * k + 1] != 0) nz++;
        if (ei32[2 * (EE / 2 + k) + 1] != 0) nz++;
    }
    atomicAdd(&cnt, nz);
    __syncthreads();
    if (threadIdx.x == 0) g_is64 = (cnt < 2048) ? 1 : 0;
}

__device__ __forceinline__ int load_idx(const void* ei, size_t pos, int is64) {
    if (is64) return (int)((const long long*)ei)[pos];
    return ((const int*)ei)[pos];
}

// -------- zero counters --------
__global__ void zero_kernel() {
    int i = blockIdx.x * blockDim.x + threadIdx.x;
    if (i < NN) { g_deg[i] = 0.0f; g_cnt[i] = 0; g_cur[i] = 0; }
    if (i == 0) g_total = 0;
}

// -------- fused: safe edge weights + degree/count accumulation --------
__global__ void ewdeg_kernel(const float* __restrict__ ew_in,
                             const void* __restrict__ ei) {
    int e = blockIdx.x * blockDim.x + threadIdx.x;
    if (e >= EE) return;
    float w = fmaxf(fabsf(fsafe(ew_in[e])), 1e-6f);
    g_ew[e] = w;
    int is64 = g_is64;
    int c = load_idx(ei, (size_t)EE + e, is64);
    if ((unsigned)c < NN) {
        atomicAdd(&g_deg[c], w);
        atomicAdd(&g_cnt[c], 1);
    }
}

// -------- fused: dis = rsqrt(deg+1) + segment placement scan --------
__global__ void disscan_kernel() {
    __shared__ int warp_tot[8];
    __shared__ int blk_base;
    int n = blockIdx.x * 256 + threadIdx.x;
    int lane = threadIdx.x & 31, w = threadIdx.x >> 5;

    if (n < NN) g_dis[n] = rsqrtf(g_deg[n] + 1.0f);

    int c = (n < NN) ? g_cnt[n] : 0;
    int incl = c;
    #pragma unroll
    for (int o = 1; o < 32; o <<= 1) {
        int t = __shfl_up_sync(0xffffffffu, incl, o);
        if (lane >= o) incl += t;
    }
    if (lane == 31) warp_tot[w] = incl;
    __syncthreads();
    if (w == 0) {
        int t = (lane < 8) ? warp_tot[lane] : 0;
        #pragma unroll
        for (int o = 1; o < 8; o <<= 1) {
            int u = __shfl_up_sync(0xffffffffu, t, o);
            if (lane >= o) t += u;
        }
        if (lane < 8) warp_tot[lane] = t;
        if (lane == 7) blk_base = atomicAdd(&g_total, t);
    }
    __syncthreads();
    int prefix = blk_base + (w > 0 ? warp_tot[w - 1] : 0) + incl - c;
    if (n < NN) g_off[n] = prefix;
}

// -------- CSR fill --------
__global__ void fill_kernel(const void* __restrict__ ei) {
    int e = blockIdx.x * blockDim.x + threadIdx.x;
    if (e >= EE) return;
    int is64 = g_is64;
    int r = load_idx(ei, (size_t)e, is64);
    int c = load_idx(ei, (size_t)EE + e, is64);
    if ((unsigned)r >= NN || (unsigned)c >= NN) return;
    float norm = g_dis[r] * g_ew[e] * g_dis[c];
    int p = atomicAdd(&g_cur[c], 1);
    int slot = g_off[c] + p;
    if ((unsigned)slot < EE) {
        g_erow[slot]  = r;
        g_enorm[slot] = norm;
    }
}

// -------- h = safe(x) --------
__global__ void copyx_kernel(const float* __restrict__ x) {
    size_t i = (size_t)blockIdx.x * blockDim.x + threadIdx.x;
    if (i < (size_t)NN * DD) g_h[i] = fsafe(x[i]);
}

// ============ tf32 tensor-core GEMM (double buffered): g_xwh = half(g_h @ W) ============
__device__ __forceinline__ uint32_t tf32r(float f) {
    uint32_t r;
    asm("cvt.rna.tf32.f32 %0, %1;" : "=r"(r) : "f"(f));
    return r;
}

__device__ __forceinline__ void mma_tf32(float* c,
                                         uint32_t a0, uint32_t a1,
                                         uint32_t a2, uint32_t a3,
                                         uint32_t b0, uint32_t b1) {
    asm volatile(
        "mma.sync.aligned.m16n8k8.row.col.f32.tf32.tf32.f32 "
        "{%0,%1,%2,%3}, {%4,%5,%6,%7}, {%8,%9}, {%0,%1,%2,%3};"
        : "+f"(c[0]), "+f"(c[1]), "+f"(c[2]), "+f"(c[3])
        : "r"(a0), "r"(a1), "r"(a2), "r"(a3), "r"(b0), "r"(b1));
}

#define GEMM_SMEM_WORDS (2 * 32 * 132 * 2)
#define GEMM_SMEM_BYTES (GEMM_SMEM_WORDS * 4)

__global__ __launch_bounds__(256) void tf32gemm_kernel(const float* __restrict__ W) {
    extern __shared__ uint32_t smem[];
    // layout: As[2][32][132] then Bs[2][32][132]
    uint32_t (*As)[32][132] = (uint32_t (*)[32][132])smem;
    uint32_t (*Bs)[32][132] = (uint32_t (*)[32][132])(smem + 2 * 32 * 132);

    const int tid  = threadIdx.x;
    const int wid  = tid >> 5;
    const int lane = tid & 31;
    const int wm   = wid & 3;
    const int wn   = wid >> 2;
    const int m0   = blockIdx.x * 128;
    const int n0   = blockIdx.y * 128;

    const int lr = lane >> 2;
    const int lc = lane & 3;

    const int arow = tid >> 1;
    const int ac4  = (tid & 1) * 4;
    const int bk   = tid >> 3;
    const int bc0  = tid & 7;

    const int grow = m0 + arow;
    const bool arow_ok = (grow < NN);

    float acc[2][8][4] = {};
    float4 ra[4], rb[4];

    // ---- prologue: load k0=0 into regs, store into buffer 0 ----
    #pragma unroll
    for (int i = 0; i < 4; i++) {
        ra[i] = arow_ok ? *(const float4*)(g_h + (size_t)grow * DD + (ac4 + i) * 4)
                        : make_float4(0.f, 0.f, 0.f, 0.f);
        rb[i] = *(const float4*)(W + (size_t)bk * DD + n0 + (bc0 + i * 8) * 4);
    }
    #pragma unroll
    for (int i = 0; i < 4; i++) {
        int c4 = ac4 + i;
        As[0][c4 * 4 + 0][arow] = tf32r(ra[i].x);
        As[0][c4 * 4 + 1][arow] = tf32r(ra[i].y);
        As[0][c4 * 4 + 2][arow] = tf32r(ra[i].z);
        As[0][c4 * 4 + 3][arow] = tf32r(ra[i].w);
        int c4b = bc0 + i * 8;
        uint4 u;
        u.x = tf32r(rb[i].x); u.y = tf32r(rb[i].y);
        u.z = tf32r(rb[i].z); u.w = tf32r(rb[i].w);
        *(uint4*)&Bs[0][bk][c4b * 4] = u;
    }
    __syncthreads();

    int cur = 0;
    for (int k0 = 32; k0 <= DD; k0 += 32) {
        // prefetch next tile into regs (skip on last iter)
        if (k0 < DD) {
            #pragma unroll
            for (int i = 0; i < 4; i++) {
                ra[i] = arow_ok ? *(const float4*)(g_h + (size_t)grow * DD + k0 + (ac4 + i) * 4)
                                : make_float4(0.f, 0.f, 0.f, 0.f);
                rb[i] = *(const float4*)(W + (size_t)(k0 + bk) * DD + n0 + (bc0 + i * 8) * 4);
            }
        }

        // compute on current buffer
        #pragma unroll
        for (int k8 = 0; k8 < 32; k8 += 8) {
            uint32_t b[8][2];
            #pragma unroll
            for (int nt = 0; nt < 8; nt++) {
                int ncol = wn * 64 + nt * 8 + lr;
                b[nt][0] = Bs[cur][k8 + lc][ncol];
                b[nt][1] = Bs[cur][k8 + 4 + lc][ncol];
            }
            #pragma unroll
            for (int mt = 0; mt < 2; mt++) {
                int mrow = wm * 32 + mt * 16 + lr;
                uint32_t a0 = As[cur][k8 + lc][mrow];
                uint32_t a1 = As[cur][k8 + lc][mrow + 8];
                uint32_t a2 = As[cur][k8 + 4 + lc][mrow];
                uint32_t a3 = As[cur][k8 + 4 + lc][mrow + 8];
                #pragma unroll
                for (int nt = 0; nt < 8; nt++)
                    mma_tf32(acc[mt][nt], a0, a1, a2, a3, b[nt][0], b[nt][1]);
            }
        }

        if (k0 < DD) {
            int nxt = cur ^ 1;
            #pragma unroll
            for (int i = 0; i < 4; i++) {
                int c4 = ac4 + i;
                As[nxt][c4 * 4 + 0][arow] = tf32r(ra[i].x);
                As[nxt][c4 * 4 + 1][arow] = tf32r(ra[i].y);
                As[nxt][c4 * 4 + 2][arow] = tf32r(ra[i].z);
                As[nxt][c4 * 4 + 3][arow] = tf32r(ra[i].w);
                int c4b = bc0 + i * 8;
                uint4 u;
                u.x = tf32r(rb[i].x); u.y = tf32r(rb[i].y);
                u.z = tf32r(rb[i].z); u.w = tf32r(rb[i].w);
                *(uint4*)&Bs[nxt][bk][c4b * 4] = u;
            }
            __syncthreads();
            cur = nxt;
        }
    }

    // epilogue: half2 stores
    #pragma unroll
    for (int mt = 0; mt < 2; mt++) {
        int r0 = m0 + wm * 32 + mt * 16 + lr;
        #pragma unroll
        for (int nt = 0; nt < 8; nt++) {
            int c = n0 + wn * 64 + nt * 8 + lc * 2;
            if (r0 < NN)
                *(__half2*)(g_xwh + (size_t)r0 * DD + c) =
                    __floats2half2_rn(acc[mt][nt][0], acc[mt][nt][1]);
            if (r0 + 8 < NN)
                *(__half2*)(g_xwh + (size_t)(r0 + 8) * DD + c) =
                    __floats2half2_rn(acc[mt][nt][2], acc[mt][nt][3]);
        }
    }
}

// -------- fused gather-aggregate + bias + LayerNorm + ReLU + residual --------
__device__ __forceinline__ float warp_sum(float v) {
    #pragma unroll
    for (int o = 16; o > 0; o >>= 1) v += __shfl_xor_sync(0xffffffffu, v, o);
    return v;
}

__device__ __forceinline__ void fma8(float* a, float w, uint4 u) {
    __half2* h = (__half2*)&u;
    float2 p0 = __half22float2(h[0]);
    float2 p1 = __half22float2(h[1]);
    float2 p2 = __half22float2(h[2]);
    float2 p3 = __half22float2(h[3]);
    a[0] = fmaf(w, p0.x, a[0]); a[1] = fmaf(w, p0.y, a[1]);
    a[2] = fmaf(w, p1.x, a[2]); a[3] = fmaf(w, p1.y, a[3]);
    a[4] = fmaf(w, p2.x, a[4]); a[5] = fmaf(w, p2.y, a[5]);
    a[6] = fmaf(w, p3.x, a[6]); a[7] = fmaf(w, p3.y, a[7]);
}

__global__ void agg_ln_kernel(const float* __restrict__ bias,
                              const float* __restrict__ gam,
                              const float* __restrict__ bet,
                              float* __restrict__ outp /* may be null */) {
    int warp = (blockIdx.x * blockDim.x + threadIdx.x) >> 5;
    if (warp >= NN) return;
    int lane = threadIdx.x & 31;

    const uint4* xwv = (const uint4*)g_xwh;
    size_t base = (size_t)warp * 32;

    float a[8] = {};
    float s = g_dis[warp]; s = s * s;
    fma8(a, s, xwv[base + lane]);

    int off = g_off[warp];
    int cnt = g_cnt[warp];
    int i = 0;
    for (; i + 4 <= cnt; i += 4) {
        int   r0 = g_erow[off + i];
        int   r1 = g_erow[off + i + 1];
        int   r2 = g_erow[off + i + 2];
        int   r3 = g_erow[off + i + 3];
        float w0 = g_enorm[off + i];
        float w1 = g_enorm[off + i + 1];
        float w2 = g_enorm[off + i + 2];
        float w3 = g_enorm[off + i + 3];
        uint4 u0 = xwv[(size_t)r0 * 32 + lane];
        uint4 u1 = xwv[(size_t)r1 * 32 + lane];
        uint4 u2 = xwv[(size_t)r2 * 32 + lane];
        uint4 u3 = xwv[(size_t)r3 * 32 + lane];
        fma8(a, w0, u0);
        fma8(a, w1, u1);
        fma8(a, w2, u2);
        fma8(a, w3, u3);
    }
    for (; i < cnt; i++) {
        int   r = g_erow[off + i];
        float w = g_enorm[off + i];
        fma8(a, w, xwv[(size_t)r * 32 + lane]);
    }

    const float4* b4 = (const float4*)bias;
    float4 bb0 = b4[lane * 2], bb1 = b4[lane * 2 + 1];
    float t[8];
    t[0] = fsafe(a[0] + bb0.x); t[1] = fsafe(a[1] + bb0.y);
    t[2] = fsafe(a[2] + bb0.z); t[3] = fsafe(a[3] + bb0.w);
    t[4] = fsafe(a[4] + bb1.x); t[5] = fsafe(a[5] + bb1.y);
    t[6] = fsafe(a[6] + bb1.z); t[7] = fsafe(a[7] + bb1.w);

    float ls = t[0] + t[1] + t[2] + t[3] + t[4] + t[5] + t[6] + t[7];
    float mu = warp_sum(ls) * (1.0f / DD);
    float lv = 0.0f;
    #pragma unroll
    for (int j = 0; j < 8; j++) { float d = t[j] - mu; lv = fmaf(d, d, lv); }
    float var = warp_sum(lv) * (1.0f / DD);
    float inv = rsqrtf(var + LN_EPS);

    const float4* g4 = (const float4*)gam;
    const float4* e4 = (const float4*)bet;
    float4 gg0 = g4[lane * 2], gg1 = g4[lane * 2 + 1];
    float4 ee0 = e4[lane * 2], ee1 = e4[lane * 2 + 1];
    float gv[8] = {gg0.x, gg0.y, gg0.z, gg0.w, gg1.x, gg1.y, gg1.z, gg1.w};
    float ev[8] = {ee0.x, ee0.y, ee0.z, ee0.w, ee1.x, ee1.y, ee1.z, ee1.w};

    float4* h4 = (float4*)g_h;
    size_t hbase = (size_t)warp * 64 + lane * 2;
    float4 r0 = h4[hbase], r1 = h4[hbase + 1];
    float rv[8] = {r0.x, r0.y, r0.z, r0.w, r1.x, r1.y, r1.z, r1.w};

    float o[8];
    #pragma unroll
    for (int j = 0; j < 8; j++) {
        float y = fsafe((t[j] - mu) * inv * gv[j] + ev[j]);
        y = fmaxf(y, 0.0f);
        o[j] = fsafe(y + rv[j]);
    }

    float4 w0 = make_float4(o[0], o[1], o[2], o[3]);
    float4 w1 = make_float4(o[4], o[5], o[6], o[7]);
    h4[hbase] = w0;
    h4[hbase + 1] = w1;
    if (outp) {
        float4* o4 = (float4*)outp;
        o4[hbase] = w0;
        o4[hbase + 1] = w1;
    }
}

// ---------------------------------------------------------------------------
extern "C" void kernel_launch(void* const* d_in, const int* in_sizes, int n_in,
                              void* d_out, int out_size) {
    const float* x   = (const float*)d_in[0];
    const void*  ei  = d_in[1];
    const float* ew  = (const float*)d_in[2];
    const float* W1  = (const float*)d_in[3];
    const float* b1  = (const float*)d_in[4];
    const float* g1  = (const float*)d_in[5];
    const float* be1 = (const float*)d_in[6];
    const float* W2  = (const float*)d_in[7];
    const float* b2  = (const float*)d_in[8];
    const float* g2  = (const float*)d_in[9];
    const float* be2 = (const float*)d_in[10];
    float* out = (float*)d_out;

    cudaFuncSetAttribute(tf32gemm_kernel,
                         cudaFuncAttributeMaxDynamicSharedMemorySize,
                         GEMM_SMEM_BYTES);

    const int T = 256;
    const int edge_blocks = (EE + T - 1) / T;
    const int nd_blocks   = (int)(((size_t)NN * DD + T - 1) / T);
    const int node_blocks = (NN + T - 1) / T;
    dim3 gemm_grid((NN + 127) / 128, DD / 128);
    const int aggr_blocks = (NN * 32 + T - 1) / T;

    detect_kernel<<<1, 256>>>((const int*)ei);
    zero_kernel<<<node_blocks, T>>>();
    ewdeg_kernel<<<edge_blocks, T>>>(ew, ei);
    disscan_kernel<<<node_blocks, T>>>();
    fill_kernel<<<edge_blocks, T>>>(ei);
    copyx_kernel<<<nd_blocks, T>>>(x);

    // ---- layer 1 ----
    tf32gemm_kernel<<<gemm_grid, T, GEMM_SMEM_BYTES>>>(W1);
    agg_ln_kernel<<<aggr_blocks, T>>>(b1, g1, be1, nullptr);

    // ---- layer 2 ----
    tf32gemm_kernel<<<gemm_grid, T, GEMM_SMEM_BYTES>>>(W2);
    agg_ln_kernel<<<aggr_blocks, T>>>(b2, g2, be2, out);
}